// round 10
// baseline (speedup 1.0000x reference)
#include <cuda_runtime.h>
#include <math_constants.h>

// Problem shape (fixed by the dataset)
#define BB 4
#define HH 32
#define DD 128
#define SS 8192
#define NBH (BB * HH)     // 128
#define RANKS 32          // warps per (b,h) group -> grid = 128*32/2 = 2048 CTAs
#define NCHUNK 128        // stealable chunks per (b,h); ~4 per warp
#define SCALE 0.08838834764831845f   // 1/sqrt(128)

// Scratch (device globals: allocation-free)
__device__ int   g_chunk[NBH];               // steal counters (reset by combiner)
__device__ int   g_done[NBH];                // flushed-warp counters (reset by combiner)
__device__ float g_pm[NBH * RANKS];
__device__ float g_pl[NBH * RANKS];
__device__ float g_pacc[(size_t)NBH * RANKS * DD];

__device__ __forceinline__ float warp_sum(float v) {
#pragma unroll
    for (int o = 16; o > 0; o >>= 1)
        v += __shfl_xor_sync(0xffffffffu, v, o);
    return v;
}

__device__ __forceinline__ float dot4(const float4 a, const float4 b) {
    return a.x * b.x + a.y * b.y + a.z * b.z + a.w * b.w;
}

__device__ __forceinline__ float4 ldcs4(const float* p) {
    return __ldcs(reinterpret_cast<const float4*>(p));
}

// ---------------------------------------------------------------------------
// Warp gw is bound to bh = gw % 128 (rank = gw / 128; 32 warps per bh, spread
// across SMs since consecutive CTAs hold consecutive bh). Warps STEAL 32-pos
// chunks of their bh via atomicAdd and accumulate online-softmax state across
// chunks (no per-chunk flush). Inner loop identical to the measured-best R6:
// 4x position unroll, 8 streaming float4 loads in flight, lane owns 4 dims.
// Every warp writes exactly one partial to slot (bh, rank); the 32nd warp to
// finish combines and writes the output, then resets the two counters.
// ---------------------------------------------------------------------------
__global__ __launch_bounds__(64)
void attn_steal_kernel(const float* __restrict__ x,
                       const float* __restrict__ kv,
                       const int*   __restrict__ cur_pos,
                       float*       __restrict__ out) {
    const int gw   = blockIdx.x * 2 + (threadIdx.x >> 5);
    const int bh   = gw & (NBH - 1);
    const int rank = gw >> 7;                // 0..RANKS-1
    const int lane = threadIdx.x & 31;
    const int h    = bh % HH;
    const int b    = bh / HH;

    const int len = *cur_pos + 1;            // valid positions
    const int CH  = (len + NCHUNK - 1) / NCHUNK;

    // q[b,0,h,:] — lane's 4 dims
    const float4 q = *reinterpret_cast<const float4*>(
        x + (size_t)(b * HH + h) * DD + lane * 4);

    const size_t row_stride = (size_t)HH * DD;           // stride over s
    const size_t kv_half    = (size_t)BB * SS * HH * DD; // K->V offset
    const float* Kp = kv + (size_t)b * SS * row_stride + (size_t)h * DD + lane * 4;
    const float* Vp = Kp + kv_half;

    float  m = -CUDART_INF_F;
    float  l = 0.f;
    float4 acc = make_float4(0.f, 0.f, 0.f, 0.f);

    // ---- steal chunks of this bh until exhausted ----
    for (;;) {
        int idx = 0;
        if (lane == 0) idx = atomicAdd(&g_chunk[bh], 1);
        idx = __shfl_sync(0xffffffffu, idx, 0);
        if (idx >= NCHUNK) break;

        const int s0 = idx * CH;
        const int s1 = min(len, s0 + CH);

        int s = s0;
        // 4x unroll: 8 streaming float4 loads in flight before dependent math.
        for (; s + 3 < s1; s += 4) {
            const float4 k0 = ldcs4(Kp + (size_t)(s    ) * row_stride);
            const float4 v0 = ldcs4(Vp + (size_t)(s    ) * row_stride);
            const float4 k1 = ldcs4(Kp + (size_t)(s + 1) * row_stride);
            const float4 v1 = ldcs4(Vp + (size_t)(s + 1) * row_stride);
            const float4 k2 = ldcs4(Kp + (size_t)(s + 2) * row_stride);
            const float4 v2 = ldcs4(Vp + (size_t)(s + 2) * row_stride);
            const float4 k3 = ldcs4(Kp + (size_t)(s + 3) * row_stride);
            const float4 v3 = ldcs4(Vp + (size_t)(s + 3) * row_stride);

            const float sc0 = warp_sum(dot4(k0, q)) * SCALE;
            const float sc1 = warp_sum(dot4(k1, q)) * SCALE;
            const float sc2 = warp_sum(dot4(k2, q)) * SCALE;
            const float sc3 = warp_sum(dot4(k3, q)) * SCALE;

            const float mn = fmaxf(fmaxf(fmaxf(m, sc0), fmaxf(sc1, sc2)), sc3);
            const float corr = __expf(m - mn);
            const float p0 = __expf(sc0 - mn);
            const float p1 = __expf(sc1 - mn);
            const float p2 = __expf(sc2 - mn);
            const float p3 = __expf(sc3 - mn);
            m = mn;
            l = l * corr + ((p0 + p1) + (p2 + p3));
            acc.x = acc.x * corr + (p0 * v0.x + p1 * v1.x) + (p2 * v2.x + p3 * v3.x);
            acc.y = acc.y * corr + (p0 * v0.y + p1 * v1.y) + (p2 * v2.y + p3 * v3.y);
            acc.z = acc.z * corr + (p0 * v0.z + p1 * v1.z) + (p2 * v2.z + p3 * v3.z);
            acc.w = acc.w * corr + (p0 * v0.w + p1 * v1.w) + (p2 * v2.w + p3 * v3.w);
        }
        for (; s < s1; s++) {
            const float4 kk = ldcs4(Kp + (size_t)s * row_stride);
            const float4 vv = ldcs4(Vp + (size_t)s * row_stride);
            const float sc = warp_sum(dot4(kk, q)) * SCALE;
            const float mn   = fmaxf(m, sc);
            const float corr = __expf(m - mn);
            const float p    = __expf(sc - mn);
            m = mn;
            l = l * corr + p;
            acc.x = acc.x * corr + p * vv.x;
            acc.y = acc.y * corr + p * vv.y;
            acc.z = acc.z * corr + p * vv.z;
            acc.w = acc.w * corr + p * vv.w;
        }
    }

    // ---- every warp writes its slot (fresh each launch; l==0 if no chunks) --
    const int slot = bh * RANKS + rank;
    if (lane == 0) { g_pm[slot] = m; g_pl[slot] = l; }
    reinterpret_cast<float4*>(g_pacc + (size_t)slot * DD)[lane] = acc;

    // ---- last warp of the bh group combines ----
    __threadfence();
    int done = 0;
    if (lane == 0) done = atomicAdd(&g_done[bh], 1);
    done = __shfl_sync(0xffffffffu, done, 0);

    if (done == RANKS - 1) {
        float GM = -CUDART_INF_F;
#pragma unroll 8
        for (int i = 0; i < RANKS; i++)
            GM = fmaxf(GM, __ldcg(&g_pm[bh * RANKS + i]));

        float  GL = 0.f;
        float4 go = make_float4(0.f, 0.f, 0.f, 0.f);
#pragma unroll 4
        for (int i = 0; i < RANKS; i++) {
            const int idx = bh * RANKS + i;
            const float li = __ldcg(&g_pl[idx]);
            if (li == 0.f) continue;          // warp stole no chunks
            const float c = __expf(__ldcg(&g_pm[idx]) - GM);
            GL += c * li;
            const float4 a = __ldcg(reinterpret_cast<const float4*>(
                g_pacc + (size_t)idx * DD) + lane);
            go.x += c * a.x; go.y += c * a.y;
            go.z += c * a.z; go.w += c * a.w;
        }
        const float inv = 1.f / GL;
        const float4 r = make_float4(go.x * inv, go.y * inv,
                                     go.z * inv, go.w * inv);
        reinterpret_cast<float4*>(out + (size_t)bh * DD)[lane] = r;

        // reset this bh's counters for the next graph replay — safe: all
        // RANKS warps of this group are past stealing and flushed.
        if (lane == 0) { g_chunk[bh] = 0; g_done[bh] = 0; }
    }
}

// ---------------------------------------------------------------------------
extern "C" void kernel_launch(void* const* d_in, const int* in_sizes, int n_in,
                              void* d_out, int out_size) {
    // Identify inputs defensively by element count:
    //   x: B*H*D = 16384 fp32, kv: 2*B*S*H*D fp32 (largest), current_pos: 1 int
    const float* x  = nullptr;
    const float* kv = nullptr;
    const int*   cp = nullptr;
    long long best_kv = -1;
    for (int i = 0; i < n_in; i++) {
        if (in_sizes[i] == 1) cp = (const int*)d_in[i];
        else if (in_sizes[i] == BB * HH * DD) x = (const float*)d_in[i];
        else if ((long long)in_sizes[i] > best_kv) {
            best_kv = in_sizes[i];
            kv = (const float*)d_in[i];
        }
    }

    attn_steal_kernel<<<NBH * RANKS / 2, 64>>>(x, kv, cp, (float*)d_out);
}

// round 11
// speedup vs baseline: 1.0965x; 1.0965x over previous
#include <cuda_runtime.h>
#include <math_constants.h>

// Problem shape (fixed by the dataset)
#define BB 4
#define HH 32
#define DD 128
#define SS 8192
#define NSPLITS 16        // measured-optimal granularity; grid = 2048 CTAs
#define NWARPS 2          // 64-thread CTAs -> ~28 warps/SM, single wave
#define NBH (BB * HH)     // 128
#define SCALE 0.08838834764831845f   // 1/sqrt(128)

// Scratch for split-KV partials (device globals: allocation-free)
__device__ float g_pm[NBH * NSPLITS];
__device__ float g_pl[NBH * NSPLITS];
__device__ float g_pacc[NBH * NSPLITS * DD];
__device__ int   g_cnt[NBH];   // zero-init; self-resetting -> graph-replay safe

__device__ __forceinline__ float warp_sum(float v) {
#pragma unroll
    for (int o = 16; o > 0; o >>= 1)
        v += __shfl_xor_sync(0xffffffffu, v, o);
    return v;
}

__device__ __forceinline__ float dot4(const float4 a, const float4 b) {
    return a.x * b.x + a.y * b.y + a.z * b.z + a.w * b.w;
}

__device__ __forceinline__ float4 ldcs4(const float* p) {
    return __ldcs(reinterpret_cast<const float4*>(p));
}

// ---------------------------------------------------------------------------
// MEASURED OPTIMUM (R6 config, 82.4us @ ~79% DRAM of 8TB/s spec).
// One CTA = one (b, h, split). Warps stride positions inside the split chunk.
// Lane owns dims [4*lane, 4*lane+4). 4x position unroll -> 8 streaming float4
// loads in flight per warp. Fused combine: last CTA per (b,h) merges partials.
// Falsified alternatives: higher occupancy (R3), lower MLP (R5), larger DRAM
// granule (R4/R8), single-warp CTAs (R9), dynamic work-stealing (R10).
// ---------------------------------------------------------------------------
__global__ __launch_bounds__(NWARPS * 32)
void attn_split_kernel(const float* __restrict__ x,
                       const float* __restrict__ kv,
                       const int*   __restrict__ cur_pos,
                       float*       __restrict__ out) {
    const int bid   = blockIdx.x;            // bh*NSPLITS + split
    const int bh    = bid / NSPLITS;
    const int h     = bh % HH;
    const int b     = bh / HH;
    const int split = bid % NSPLITS;

    const int tid  = threadIdx.x;
    const int lane = tid & 31;
    const int w    = tid >> 5;

    const int len   = *cur_pos + 1;                      // valid positions
    const int chunk = (len + NSPLITS - 1) / NSPLITS;
    const int s0    = split * chunk;
    const int s1    = min(len, s0 + chunk);

    // q[b,0,h,:] — lane's 4 dims
    const float4 q = *reinterpret_cast<const float4*>(
        x + (size_t)(b * HH + h) * DD + lane * 4);

    const size_t row_stride = (size_t)HH * DD;           // stride over s
    const size_t kv_half    = (size_t)BB * SS * HH * DD; // K->V offset
    const float* Kp = kv + (size_t)b * SS * row_stride + (size_t)h * DD + lane * 4;
    const float* Vp = Kp + kv_half;

    float  m = -CUDART_INF_F;
    float  l = 0.f;
    float4 acc = make_float4(0.f, 0.f, 0.f, 0.f);

    int s = s0 + w;
    // 4x unroll: 8 streaming float4 loads in flight before dependent math,
    // single max/rescale per group -> 4 independent __expf's.
    for (; s + 3 * NWARPS < s1; s += 4 * NWARPS) {
        const float4 k0 = ldcs4(Kp + (size_t)(s             ) * row_stride);
        const float4 v0 = ldcs4(Vp + (size_t)(s             ) * row_stride);
        const float4 k1 = ldcs4(Kp + (size_t)(s +     NWARPS) * row_stride);
        const float4 v1 = ldcs4(Vp + (size_t)(s +     NWARPS) * row_stride);
        const float4 k2 = ldcs4(Kp + (size_t)(s + 2 * NWARPS) * row_stride);
        const float4 v2 = ldcs4(Vp + (size_t)(s + 2 * NWARPS) * row_stride);
        const float4 k3 = ldcs4(Kp + (size_t)(s + 3 * NWARPS) * row_stride);
        const float4 v3 = ldcs4(Vp + (size_t)(s + 3 * NWARPS) * row_stride);

        const float sc0 = warp_sum(dot4(k0, q)) * SCALE;
        const float sc1 = warp_sum(dot4(k1, q)) * SCALE;
        const float sc2 = warp_sum(dot4(k2, q)) * SCALE;
        const float sc3 = warp_sum(dot4(k3, q)) * SCALE;

        const float mn = fmaxf(fmaxf(fmaxf(m, sc0), fmaxf(sc1, sc2)), sc3);
        const float corr = __expf(m - mn);
        const float p0 = __expf(sc0 - mn);
        const float p1 = __expf(sc1 - mn);
        const float p2 = __expf(sc2 - mn);
        const float p3 = __expf(sc3 - mn);
        m = mn;
        l = l * corr + ((p0 + p1) + (p2 + p3));
        acc.x = acc.x * corr + (p0 * v0.x + p1 * v1.x) + (p2 * v2.x + p3 * v3.x);
        acc.y = acc.y * corr + (p0 * v0.y + p1 * v1.y) + (p2 * v2.y + p3 * v3.y);
        acc.z = acc.z * corr + (p0 * v0.z + p1 * v1.z) + (p2 * v2.z + p3 * v3.z);
        acc.w = acc.w * corr + (p0 * v0.w + p1 * v1.w) + (p2 * v2.w + p3 * v3.w);
    }
    for (; s < s1; s += NWARPS) {
        const float4 kk = ldcs4(Kp + (size_t)s * row_stride);
        const float4 vv = ldcs4(Vp + (size_t)s * row_stride);
        const float sc = warp_sum(dot4(kk, q)) * SCALE;
        const float mn   = fmaxf(m, sc);
        const float corr = __expf(m - mn);
        const float p    = __expf(sc - mn);
        m = mn;
        l = l * corr + p;
        acc.x = acc.x * corr + p * vv.x;
        acc.y = acc.y * corr + p * vv.y;
        acc.z = acc.z * corr + p * vv.z;
        acc.w = acc.w * corr + p * vv.w;
    }

    // ---- combine the NWARPS warps of this CTA ----
    __shared__ float sm_m[NWARPS];
    __shared__ float sm_l[NWARPS];
    __shared__ float sm_acc[NWARPS][DD];

    if (lane == 0) { sm_m[w] = m; sm_l[w] = l; }
    sm_acc[w][lane * 4 + 0] = acc.x;
    sm_acc[w][lane * 4 + 1] = acc.y;
    sm_acc[w][lane * 4 + 2] = acc.z;
    sm_acc[w][lane * 4 + 3] = acc.w;
    __syncthreads();

    if (w == 0) {
        float M = -CUDART_INF_F;
#pragma unroll
        for (int i = 0; i < NWARPS; i++) M = fmaxf(M, sm_m[i]);

        float  L = 0.f;
        float4 o = make_float4(0.f, 0.f, 0.f, 0.f);
#pragma unroll
        for (int i = 0; i < NWARPS; i++) {
            if (sm_l[i] == 0.f) continue;   // warp saw no positions
            const float c = __expf(sm_m[i] - M);
            L += c * sm_l[i];
            o.x += c * sm_acc[i][lane * 4 + 0];
            o.y += c * sm_acc[i][lane * 4 + 1];
            o.z += c * sm_acc[i][lane * 4 + 2];
            o.w += c * sm_acc[i][lane * 4 + 3];
        }
        g_pm[bid] = M;
        g_pl[bid] = L;
        reinterpret_cast<float4*>(g_pacc + (size_t)bid * DD)[lane] = o;

        // ---- fused cross-split combine: last CTA per (b,h) merges ----
        __threadfence();
        int done = 0;
        if (lane == 0) done = atomicAdd(&g_cnt[bh], 1);
        done = __shfl_sync(0xffffffffu, done, 0);

        if (done == NSPLITS - 1) {
            float GM = -CUDART_INF_F;
#pragma unroll
            for (int i = 0; i < NSPLITS; i++)
                GM = fmaxf(GM, __ldcg(&g_pm[bh * NSPLITS + i]));

            float  GL = 0.f;
            float4 go = make_float4(0.f, 0.f, 0.f, 0.f);
#pragma unroll 4
            for (int i = 0; i < NSPLITS; i++) {
                const int idx = bh * NSPLITS + i;
                const float li = __ldcg(&g_pl[idx]);
                if (li == 0.f) continue;
                const float c = __expf(__ldcg(&g_pm[idx]) - GM);
                GL += c * li;
                const float4 a = __ldcg(reinterpret_cast<const float4*>(
                    g_pacc + (size_t)idx * DD) + lane);
                go.x += c * a.x; go.y += c * a.y;
                go.z += c * a.z; go.w += c * a.w;
            }
            const float inv = 1.f / GL;
            const float4 r = make_float4(go.x * inv, go.y * inv,
                                         go.z * inv, go.w * inv);
            reinterpret_cast<float4*>(out + (size_t)bh * DD)[lane] = r;

            if (lane == 0) g_cnt[bh] = 0;   // reset for next graph replay
        }
    }
}

// ---------------------------------------------------------------------------
extern "C" void kernel_launch(void* const* d_in, const int* in_sizes, int n_in,
                              void* d_out, int out_size) {
    // Identify inputs defensively by element count:
    //   x: B*H*D = 16384 fp32, kv: 2*B*S*H*D fp32 (largest), current_pos: 1 int
    const float* x  = nullptr;
    const float* kv = nullptr;
    const int*   cp = nullptr;
    long long best_kv = -1;
    for (int i = 0; i < n_in; i++) {
        if (in_sizes[i] == 1) cp = (const int*)d_in[i];
        else if (in_sizes[i] == BB * HH * DD) x = (const float*)d_in[i];
        else if ((long long)in_sizes[i] > best_kv) {
            best_kv = in_sizes[i];
            kv = (const float*)d_in[i];
        }
    }

    attn_split_kernel<<<NBH * NSPLITS, NWARPS * 32>>>(x, kv, cp, (float*)d_out);
}